// round 9
// baseline (speedup 1.0000x reference)
#include <cuda_runtime.h>
#include <math_constants.h>

// Problem constants (fixed by the reference setup)
#define NN    50000
#define EE    1600000
#define DIN   128
#define DOUT  128
#define HH    8
#define DHH   16
#define DGG   64
#define BCOLS 352   // padded: 64 zj | 128 f0 | 128 f1 | 8 fz | 24 pad

// ---------------- device scratch (no allocation allowed) ----------------
__device__ float  g_B[DIN * BCOLS];    // prepacked GEMM B
__device__ float  g_zj[NN * DGG];      // feat @ Wpg              [N,64]
__device__ float  g_f0[NN * DOUT];     // relu(feat@W0 + b0)      [N,128]
__device__ float  g_f1[NN * DOUT];     // relu(feat@W1 + b1)      [N,128]
__device__ float  g_fz[NN * HH];       // feat @ wg[192:320]      [N,8]
__device__ float  g_aself[NN * HH];    // leaky(f0 . att_self)    [N,8]
__device__ float  g_aneigh[NN * HH];   // leaky(f1 . att_neigh)   [N,8]
__device__ int    g_cnt[NN];
__device__ int    g_ptr[NN + 1];
__device__ int    g_pos[NN];
__device__ unsigned long long g_edge[EE];  // packed (val<<32 | col), CSR order

// ---------------- CSR build ----------------
__global__ void k_zero_cnt() {
    int i = blockIdx.x * blockDim.x + threadIdx.x;
    if (i < NN) g_cnt[i] = 0;
}

__global__ void k_hist(const int* __restrict__ row) {
    int i = blockIdx.x * blockDim.x + threadIdx.x;
    if (i < EE) atomicAdd(&g_cnt[row[i]], 1);
}

__global__ void k_scan() {
    __shared__ int wsum[32];
    __shared__ int s_carry;
    int tid  = threadIdx.x;
    int lane = tid & 31;
    int wid  = tid >> 5;
    if (tid == 0) s_carry = 0;
    __syncthreads();
    for (int base = 0; base < NN; base += 1024) {
        int i = base + tid;
        int x = (i < NN) ? g_cnt[i] : 0;
        int v = x;
        #pragma unroll
        for (int off = 1; off < 32; off <<= 1) {
            int t = __shfl_up_sync(0xffffffffu, v, off);
            if (lane >= off) v += t;
        }
        if (lane == 31) wsum[wid] = v;
        __syncthreads();
        if (wid == 0) {
            int s = wsum[lane];
            #pragma unroll
            for (int off = 1; off < 32; off <<= 1) {
                int t = __shfl_up_sync(0xffffffffu, s, off);
                if (lane >= off) s += t;
            }
            wsum[lane] = s;
        }
        __syncthreads();
        int incl  = v + (wid > 0 ? wsum[wid - 1] : 0);
        int carry = s_carry;
        if (i < NN) {
            int e = carry + incl - x;
            g_ptr[i] = e;
            g_pos[i] = e;
        }
        __syncthreads();
        if (tid == 1023) s_carry = carry + incl;
        __syncthreads();
    }
    if (tid == 0) g_ptr[NN] = s_carry;
}

__global__ void k_scatter(const int* __restrict__ row,
                          const int* __restrict__ col,
                          const float* __restrict__ val) {
    int i = blockIdx.x * blockDim.x + threadIdx.x;
    if (i < EE) {
        int p = atomicAdd(&g_pos[row[i]], 1);
        unsigned long long pk =
            ((unsigned long long)__float_as_uint(val[i]) << 32) |
            (unsigned long long)(unsigned)col[i];
        g_edge[p] = pk;
    }
}

// ---------------- pack B once: [128][352] ----------------
__global__ void k_pack(const float* __restrict__ Wpg,
                       const float* __restrict__ W,
                       const float* __restrict__ wg) {
    int idx = blockIdx.x * blockDim.x + threadIdx.x;
    if (idx >= DIN * BCOLS) return;
    int k = idx / BCOLS, c = idx - k * BCOLS;
    float w = 0.f;
    if (c < DGG) {
        w = Wpg[k * DGG + c];
    } else if (c < 320) {
        int j  = c - DGG;
        int o  = j >> 7;
        int jj = j & 127;
        int h  = jj >> 4, kb = jj & 15;
        w = W[((o * HH + h) * DIN + k) * DHH + kb];
    } else if (c < 328) {
        w = wg[(192 + k) * HH + (c - 320)];
    }
    g_B[idx] = w;
}

// ---------------- GEMM: [N,128] x [128,352] (packed B) ----------------
#define KC 16
__global__ void __launch_bounds__(256, 2)
k_gemm(const float* __restrict__ feat, const float* __restrict__ b) {
    __shared__ float As[32][KC + 1];
    __shared__ float Bs[KC][BCOLS];
    int tid  = threadIdx.x;
    int row0 = blockIdx.x * 32;
    int rg = tid >> 5;   // warp id -> 4 rows each
    int ct = tid & 31;   // lane -> 11 cols stride 32
    float acc[4][11];
    #pragma unroll
    for (int i = 0; i < 4; i++)
        #pragma unroll
        for (int j = 0; j < 11; j++) acc[i][j] = 0.f;

    for (int kc = 0; kc < DIN; kc += KC) {
        for (int idx = tid; idx < 32 * (KC / 4); idx += 256) {
            int r = idx >> 2, q = idx & 3;
            int gr = row0 + r;
            float4 f = (gr < NN)
                ? *(const float4*)(feat + gr * DIN + kc + q * 4)
                : make_float4(0.f, 0.f, 0.f, 0.f);
            As[r][q * 4 + 0] = f.x; As[r][q * 4 + 1] = f.y;
            As[r][q * 4 + 2] = f.z; As[r][q * 4 + 3] = f.w;
        }
        for (int idx = tid; idx < KC * (BCOLS / 4); idx += 256) {
            int kk = idx / (BCOLS / 4), q = idx - kk * (BCOLS / 4);
            *((float4*)&Bs[kk][q * 4]) =
                *(const float4*)(g_B + (kc + kk) * BCOLS + q * 4);
        }
        __syncthreads();
        #pragma unroll
        for (int kk = 0; kk < KC; kk++) {
            float a[4], bb[11];
            #pragma unroll
            for (int i = 0; i < 4; i++) a[i] = As[rg * 4 + i][kk];
            #pragma unroll
            for (int j = 0; j < 11; j++) bb[j] = Bs[kk][ct + 32 * j];
            #pragma unroll
            for (int i = 0; i < 4; i++)
                #pragma unroll
                for (int j = 0; j < 11; j++) acc[i][j] += a[i] * bb[j];
        }
        __syncthreads();
    }
    #pragma unroll
    for (int i = 0; i < 4; i++) {
        int r = row0 + rg * 4 + i;
        if (r >= NN) continue;
        #pragma unroll
        for (int j = 0; j < 11; j++) {
            int c = ct + 32 * j;
            float v = acc[i][j];
            if (c < DGG) {
                g_zj[r * DGG + c] = v;
            } else if (c < 320) {
                int jj = c - DGG;
                float o = fmaxf(v + b[jj], 0.f);
                if (jj < DOUT) g_f0[r * DOUT + jj] = o;
                else           g_f1[r * DOUT + (jj - DOUT)] = o;
            } else if (c < 328) {
                g_fz[r * HH + (c - 320)] = v;
            }
        }
    }
}

// ---------------- attention scalars ----------------
__device__ __forceinline__ float leaky(float x) {
    return x >= 0.f ? x : 0.2f * x;
}

__global__ void k_att(const float* __restrict__ att) {
    int i = blockIdx.x * blockDim.x + threadIdx.x;
    if (i >= NN * HH) return;
    int n = i >> 3, h = i & 7;
    float s = 0.f, t = 0.f;
    const float* f0p = g_f0 + n * DOUT + h * DHH;
    const float* f1p = g_f1 + n * DOUT + h * DHH;
    const float* ap  = att + h * (2 * DHH);
    #pragma unroll
    for (int k = 0; k < DHH; k++) {
        s += f0p[k] * ap[k];
        t += f1p[k] * ap[DHH + k];
    }
    g_aself[i]  = leaky(s);
    g_aneigh[i] = leaky(t);
}

// ---------------- main kernel: warp-per-node, no smem, no barriers ----------------
// Lane l covers features 4l..4l+3. All per-node reductions are warp shuffles.
// __launch_bounds__(128,6): 85-reg budget so the unrolled edge loop (acc+zm+gn
// float4s + 5 base pointers + in-flight loads) does NOT spill (the R7 (128,12)
// 40-reg cap forced per-edge LDL/STL — same failure class as the R4 gemm).
__global__ void __launch_bounds__(128, 6)
k_main(const float* __restrict__ feat,
       const float* __restrict__ wg,       // [320,8]
       const float* __restrict__ scale,    // [2,128]
       const float* __restrict__ offset,   // [2,128]
       float* __restrict__ out) {
    int n = blockIdx.x * 4 + (threadIdx.x >> 5);
    if (n >= NN) return;
    int lane  = threadIdx.x & 31;
    int hlane = lane >> 2;                 // head of this lane's 4 features

    int e0 = g_ptr[n], e1 = g_ptr[n + 1];
    int deg = e1 - e0;

    float aself = g_aself[n * HH + hlane];

    float4 acc = make_float4(0.f, 0.f, 0.f, 0.f);
    float4 zm4 = make_float4(-CUDART_INF_F, -CUDART_INF_F, -CUDART_INF_F, -CUDART_INF_F);
    float4 gn4 = make_float4(0.f, 0.f, 0.f, 0.f);

    #pragma unroll 4
    for (int i = e0; i < e1; i++) {
        unsigned long long pk = g_edge[i];           // warp-uniform broadcast
        int   c = (int)(unsigned)(pk & 0xffffffffull);
        float v = __uint_as_float((unsigned)(pk >> 32));
        float a = (aself + g_aneigh[c * HH + hlane]) * v;
        float4 f = *((const float4*)(g_f1 + c * DOUT) + lane);
        acc.x += a * f.x; acc.y += a * f.y;
        acc.z += a * f.z; acc.w += a * f.w;
        if (lane < 16) {
            float4 z = *((const float4*)(g_zj + c * DGG) + lane);
            zm4.x = fmaxf(zm4.x, z.x); zm4.y = fmaxf(zm4.y, z.y);
            zm4.z = fmaxf(zm4.z, z.z); zm4.w = fmaxf(zm4.w, z.w);
        }
        if (lane < 2) {
            float4 g = *((const float4*)(g_fz + c * HH) + lane);
            gn4.x += v * g.x; gn4.y += v * g.y;
            gn4.z += v * g.z; gn4.w += v * g.w;
        }
    }

    // ---- gate: part[h] = sum_j concat[j]*wg[j][h] (features j = 4*lane..4*lane+3) ----
    float4 fv = *((const float4*)(feat + n * DIN) + lane);
    float part[8];
    #pragma unroll
    for (int hh = 0; hh < 8; hh++) part[hh] = 0.f;
    {
        int j0 = lane * 4;
        const float* wr0 = wg + (j0 + 0) * 8;
        const float* wr1 = wg + (j0 + 1) * 8;
        const float* wr2 = wg + (j0 + 2) * 8;
        const float* wr3 = wg + (j0 + 3) * 8;
        #pragma unroll
        for (int hh = 0; hh < 8; hh++)
            part[hh] += fv.x * wr0[hh] + fv.y * wr1[hh]
                      + fv.z * wr2[hh] + fv.w * wr3[hh];
    }
    if (lane < 16) {
        float zx = (deg > 0) ? zm4.x : 0.f;
        float zy = (deg > 0) ? zm4.y : 0.f;
        float zz = (deg > 0) ? zm4.z : 0.f;
        float zw = (deg > 0) ? zm4.w : 0.f;
        int j0 = lane * 4;                     // zmax feature 0..63
        const float* wr0 = wg + (128 + j0 + 0) * 8;
        const float* wr1 = wg + (128 + j0 + 1) * 8;
        const float* wr2 = wg + (128 + j0 + 2) * 8;
        const float* wr3 = wg + (128 + j0 + 3) * 8;
        #pragma unroll
        for (int hh = 0; hh < 8; hh++)
            part[hh] += zx * wr0[hh] + zy * wr1[hh]
                      + zz * wr2[hh] + zw * wr3[hh];
    }
    #pragma unroll
    for (int hh = 0; hh < 8; hh++) {
        #pragma unroll
        for (int off = 16; off > 0; off >>= 1)
            part[hh] += __shfl_xor_sync(0xffffffffu, part[hh], off);
    }
    // nmean-linearized contribution: lane0 gn4 = heads 0..3, lane1 gn4 = heads 4..7
    float g0 = __shfl_sync(0xffffffffu, gn4.x, 0);
    float g1 = __shfl_sync(0xffffffffu, gn4.y, 0);
    float g2 = __shfl_sync(0xffffffffu, gn4.z, 0);
    float g3 = __shfl_sync(0xffffffffu, gn4.w, 0);
    float g4 = __shfl_sync(0xffffffffu, gn4.x, 1);
    float g5 = __shfl_sync(0xffffffffu, gn4.y, 1);
    float g6 = __shfl_sync(0xffffffffu, gn4.z, 1);
    float g7 = __shfl_sync(0xffffffffu, gn4.w, 1);
    float gate0 = part[0] + g0, gate1 = part[1] + g1;
    float gate2 = part[2] + g2, gate3 = part[3] + g3;
    float gate4 = part[4] + g4, gate5 = part[5] + g5;
    float gate6 = part[6] + g6, gate7 = part[7] + g7;
    float gsel = (hlane == 0) ? gate0 : (hlane == 1) ? gate1
               : (hlane == 2) ? gate2 : (hlane == 3) ? gate3
               : (hlane == 4) ? gate4 : (hlane == 5) ? gate5
               : (hlane == 6) ? gate6 : gate7;

    // ---- norm + output ----
    float4 f0v = *((const float4*)(g_f0 + n * DOUT) + lane);
    float4 h1;
    h1.x = acc.x * gsel; h1.y = acc.y * gsel;
    h1.z = acc.z * gsel; h1.w = acc.w * gsel;

    float s0 = f0v.x + f0v.y + f0v.z + f0v.w;
    float q0 = f0v.x * f0v.x + f0v.y * f0v.y + f0v.z * f0v.z + f0v.w * f0v.w;
    float s1 = h1.x + h1.y + h1.z + h1.w;
    float q1 = h1.x * h1.x + h1.y * h1.y + h1.z * h1.z + h1.w * h1.w;
    #pragma unroll
    for (int off = 16; off > 0; off >>= 1) {
        s0 += __shfl_xor_sync(0xffffffffu, s0, off);
        q0 += __shfl_xor_sync(0xffffffffu, q0, off);
        s1 += __shfl_xor_sync(0xffffffffu, s1, off);
        q1 += __shfl_xor_sync(0xffffffffu, q1, off);
    }
    float mu0 = s0 * (1.f / DOUT);
    float mu1 = s1 * (1.f / DOUT);
    float r0  = rsqrtf(q0 * (1.f / DOUT) - mu0 * mu0 + 1e-9f);
    float r1  = rsqrtf(q1 * (1.f / DOUT) - mu1 * mu1 + 1e-9f);

    float4 sc0 = *((const float4*)(scale)        + lane);
    float4 sc1 = *((const float4*)(scale + DOUT) + lane);
    float4 of0 = *((const float4*)(offset)        + lane);
    float4 of1 = *((const float4*)(offset + DOUT) + lane);

    float4 o;
    o.x = (f0v.x - mu0) * r0 * sc0.x + of0.x + (h1.x - mu1) * r1 * sc1.x + of1.x;
    o.y = (f0v.y - mu0) * r0 * sc0.y + of0.y + (h1.y - mu1) * r1 * sc1.y + of1.y;
    o.z = (f0v.z - mu0) * r0 * sc0.z + of0.z + (h1.z - mu1) * r1 * sc1.z + of1.z;
    o.w = (f0v.w - mu0) * r0 * sc0.w + of0.w + (h1.w - mu1) * r1 * sc1.w + of1.w;
    *((float4*)(out + n * DOUT) + lane) = o;
}

// ---------------- launch ----------------
extern "C" void kernel_launch(void* const* d_in, const int* in_sizes, int n_in,
                              void* d_out, int out_size) {
    const int*   row    = (const int*)d_in[0];
    const int*   col    = (const int*)d_in[1];
    const float* val    = (const float*)d_in[2];
    const float* feat   = (const float*)d_in[3];
    const float* W      = (const float*)d_in[4];
    const float* b      = (const float*)d_in[5];
    const float* att    = (const float*)d_in[6];
    const float* offset = (const float*)d_in[7];
    const float* scale  = (const float*)d_in[8];
    const float* wg     = (const float*)d_in[9];
    const float* wpg    = (const float*)d_in[10];
    float* out = (float*)d_out;

    // CSR build
    k_zero_cnt<<<(NN + 255) / 256, 256>>>();
    k_hist<<<(EE + 255) / 256, 256>>>(row);
    k_scan<<<1, 1024>>>();
    k_scatter<<<(EE + 255) / 256, 256>>>(row, col, val);

    // Dense projections
    k_pack<<<(DIN * BCOLS + 255) / 256, 256>>>(wpg, W, wg);
    k_gemm<<<(NN + 31) / 32, 256>>>(feat, b);
    k_att<<<(NN * HH + 255) / 256, 256>>>(att);

    // Fused aggregate + gate + norm + output (warp per node)
    k_main<<<(NN + 3) / 4, 128>>>(feat, wg, scale, offset, out);
}

// round 10
// speedup vs baseline: 1.4145x; 1.4145x over previous
#include <cuda_runtime.h>
#include <math_constants.h>

// Problem constants (fixed by the reference setup)
#define NN    50000
#define EE    1600000
#define DIN   128
#define DOUT  128
#define HH    8
#define DHH   16
#define DGG   64
#define BCOLS 352   // padded: 64 zj | 128 f0 | 128 f1 | 8 fz | 24 pad

// ---------------- device scratch (no allocation allowed) ----------------
__device__ float  g_B[DIN * BCOLS];    // prepacked GEMM B
__device__ float  g_zj[NN * DGG];      // feat @ Wpg              [N,64]
__device__ float  g_f0[NN * DOUT];     // relu(feat@W0 + b0)      [N,128]
__device__ float  g_f1[NN * DOUT];     // relu(feat@W1 + b1)      [N,128]
__device__ float  g_fz[NN * HH];       // feat @ wg[192:320]      [N,8]
__device__ float  g_aself[NN * HH];    // leaky(f0 . att_self)    [N,8]
__device__ float  g_aneigh[NN * HH];   // leaky(f1 . att_neigh)   [N,8]
__device__ int    g_cnt[NN];
__device__ int    g_ptr[NN + 1];
__device__ int    g_pos[NN];
__device__ unsigned long long g_edge[EE];  // packed (val<<32 | col), CSR order

// ---------------- CSR build ----------------
__global__ void k_zero_cnt() {
    int i = blockIdx.x * blockDim.x + threadIdx.x;
    if (i < NN) g_cnt[i] = 0;
}

__global__ void k_hist(const int* __restrict__ row) {
    int i = blockIdx.x * blockDim.x + threadIdx.x;
    if (i < EE) atomicAdd(&g_cnt[row[i]], 1);
}

__global__ void k_scan() {
    __shared__ int wsum[32];
    __shared__ int s_carry;
    int tid  = threadIdx.x;
    int lane = tid & 31;
    int wid  = tid >> 5;
    if (tid == 0) s_carry = 0;
    __syncthreads();
    for (int base = 0; base < NN; base += 1024) {
        int i = base + tid;
        int x = (i < NN) ? g_cnt[i] : 0;
        int v = x;
        #pragma unroll
        for (int off = 1; off < 32; off <<= 1) {
            int t = __shfl_up_sync(0xffffffffu, v, off);
            if (lane >= off) v += t;
        }
        if (lane == 31) wsum[wid] = v;
        __syncthreads();
        if (wid == 0) {
            int s = wsum[lane];
            #pragma unroll
            for (int off = 1; off < 32; off <<= 1) {
                int t = __shfl_up_sync(0xffffffffu, s, off);
                if (lane >= off) s += t;
            }
            wsum[lane] = s;
        }
        __syncthreads();
        int incl  = v + (wid > 0 ? wsum[wid - 1] : 0);
        int carry = s_carry;
        if (i < NN) {
            int e = carry + incl - x;
            g_ptr[i] = e;
            g_pos[i] = e;
        }
        __syncthreads();
        if (tid == 1023) s_carry = carry + incl;
        __syncthreads();
    }
    if (tid == 0) g_ptr[NN] = s_carry;
}

__global__ void k_scatter(const int* __restrict__ row,
                          const int* __restrict__ col,
                          const float* __restrict__ val) {
    int i = blockIdx.x * blockDim.x + threadIdx.x;
    if (i < EE) {
        int p = atomicAdd(&g_pos[row[i]], 1);
        unsigned long long pk =
            ((unsigned long long)__float_as_uint(val[i]) << 32) |
            (unsigned long long)(unsigned)col[i];
        g_edge[p] = pk;
    }
}

// ---------------- pack B once: [128][352] ----------------
__global__ void k_pack(const float* __restrict__ Wpg,
                       const float* __restrict__ W,
                       const float* __restrict__ wg) {
    int idx = blockIdx.x * blockDim.x + threadIdx.x;
    if (idx >= DIN * BCOLS) return;
    int k = idx / BCOLS, c = idx - k * BCOLS;
    float w = 0.f;
    if (c < DGG) {
        w = Wpg[k * DGG + c];
    } else if (c < 320) {
        int j  = c - DGG;
        int o  = j >> 7;
        int jj = j & 127;
        int h  = jj >> 4, kb = jj & 15;
        w = W[((o * HH + h) * DIN + k) * DHH + kb];
    } else if (c < 328) {
        w = wg[(192 + k) * HH + (c - 320)];
    }
    g_B[idx] = w;
}

// ---------------- GEMM: [N,128] x [128,352] (packed B), 48 rows/block ----------------
#define KC 16
#define RTILE 48
__global__ void __launch_bounds__(256, 2)
k_gemm(const float* __restrict__ feat, const float* __restrict__ b) {
    __shared__ float As[RTILE][KC + 1];
    __shared__ float Bs[KC][BCOLS];
    int tid  = threadIdx.x;
    int row0 = blockIdx.x * RTILE;
    int rg = tid >> 5;   // warp id -> 6 rows each
    int ct = tid & 31;   // lane -> 11 cols stride 32
    float acc[6][11];
    #pragma unroll
    for (int i = 0; i < 6; i++)
        #pragma unroll
        for (int j = 0; j < 11; j++) acc[i][j] = 0.f;

    for (int kc = 0; kc < DIN; kc += KC) {
        for (int idx = tid; idx < RTILE * (KC / 4); idx += 256) {
            int r = idx >> 2, q = idx & 3;
            int gr = row0 + r;
            float4 f = (gr < NN)
                ? *(const float4*)(feat + gr * DIN + kc + q * 4)
                : make_float4(0.f, 0.f, 0.f, 0.f);
            As[r][q * 4 + 0] = f.x; As[r][q * 4 + 1] = f.y;
            As[r][q * 4 + 2] = f.z; As[r][q * 4 + 3] = f.w;
        }
        for (int idx = tid; idx < KC * (BCOLS / 4); idx += 256) {
            int kk = idx / (BCOLS / 4), q = idx - kk * (BCOLS / 4);
            *((float4*)&Bs[kk][q * 4]) =
                *(const float4*)(g_B + (kc + kk) * BCOLS + q * 4);
        }
        __syncthreads();
        #pragma unroll
        for (int kk = 0; kk < KC; kk++) {
            float a[6], bb[11];
            #pragma unroll
            for (int i = 0; i < 6; i++) a[i] = As[rg * 6 + i][kk];
            #pragma unroll
            for (int j = 0; j < 11; j++) bb[j] = Bs[kk][ct + 32 * j];
            #pragma unroll
            for (int i = 0; i < 6; i++)
                #pragma unroll
                for (int j = 0; j < 11; j++) acc[i][j] += a[i] * bb[j];
        }
        __syncthreads();
    }
    #pragma unroll
    for (int i = 0; i < 6; i++) {
        int r = row0 + rg * 6 + i;
        if (r >= NN) continue;
        #pragma unroll
        for (int j = 0; j < 11; j++) {
            int c = ct + 32 * j;
            float v = acc[i][j];
            if (c < DGG) {
                g_zj[r * DGG + c] = v;
            } else if (c < 320) {
                int jj = c - DGG;
                float o = fmaxf(v + b[jj], 0.f);
                if (jj < DOUT) g_f0[r * DOUT + jj] = o;
                else           g_f1[r * DOUT + (jj - DOUT)] = o;
            } else if (c < 328) {
                g_fz[r * HH + (c - 320)] = v;
            }
        }
    }
}

// ---------------- attention scalars ----------------
__device__ __forceinline__ float leaky(float x) {
    return x >= 0.f ? x : 0.2f * x;
}

__global__ void k_att(const float* __restrict__ att) {
    int i = blockIdx.x * blockDim.x + threadIdx.x;
    if (i >= NN * HH) return;
    int n = i >> 3, h = i & 7;
    float s = 0.f, t = 0.f;
    const float* f0p = g_f0 + n * DOUT + h * DHH;
    const float* f1p = g_f1 + n * DOUT + h * DHH;
    const float* ap  = att + h * (2 * DHH);
    #pragma unroll
    for (int k = 0; k < DHH; k++) {
        s += f0p[k] * ap[k];
        t += f1p[k] * ap[DHH + k];
    }
    g_aself[i]  = leaky(s);
    g_aneigh[i] = leaky(t);
}

// ---------------- main per-node kernel (R6 block-per-node, proven 529us) ----------------
// 4 warps; warp w handles edges i = w, w+4, ... ; lane l covers features 4l..4l+3
__global__ void __launch_bounds__(128, 12)
k_main(const float* __restrict__ feat,
       const float* __restrict__ wg,       // [320,8]
       const float* __restrict__ scale,    // [2,128]
       const float* __restrict__ offset,   // [2,128]
       float* __restrict__ out) {
    __shared__ unsigned long long s_e[128];
    __shared__ float s_agg[4][DOUT];
    __shared__ float s_z[4][DGG];
    __shared__ float s_gn[4][HH];
    __shared__ float wred[4][8];
    __shared__ float s_gate[8];
    __shared__ float red[4][4];
    __shared__ float stats[4];

    int n    = blockIdx.x;
    int tid  = threadIdx.x;
    int w    = tid >> 5;
    int lane = tid & 31;

    int e0 = g_ptr[n], e1 = g_ptr[n + 1];
    int deg = e1 - e0;

    int   hlane = lane >> 2;                     // head of this lane's 4 features
    float aself = g_aself[n * HH + hlane];

    float4 acc = make_float4(0.f, 0.f, 0.f, 0.f);
    float4 zm4 = make_float4(-CUDART_INF_F, -CUDART_INF_F, -CUDART_INF_F, -CUDART_INF_F);
    float4 gn4 = make_float4(0.f, 0.f, 0.f, 0.f);

    for (int chunk = e0; chunk < e1; chunk += 128) {
        int m = min(128, e1 - chunk);
        if (tid < m) s_e[tid] = g_edge[chunk + tid];
        __syncthreads();
        #pragma unroll 2
        for (int i = w; i < m; i += 4) {
            unsigned long long pk = s_e[i];
            int   c = (int)(unsigned)(pk & 0xffffffffull);
            float v = __uint_as_float((unsigned)(pk >> 32));
            float a = (aself + g_aneigh[c * HH + hlane]) * v;
            float4 f = *((const float4*)(g_f1 + c * DOUT) + lane);
            acc.x += a * f.x; acc.y += a * f.y;
            acc.z += a * f.z; acc.w += a * f.w;
            if (lane < 16) {
                float4 z = *((const float4*)(g_zj + c * DGG) + lane);
                zm4.x = fmaxf(zm4.x, z.x); zm4.y = fmaxf(zm4.y, z.y);
                zm4.z = fmaxf(zm4.z, z.z); zm4.w = fmaxf(zm4.w, z.w);
            }
            if (lane < 2) {
                float4 g = *((const float4*)(g_fz + c * HH) + lane);
                gn4.x += v * g.x; gn4.y += v * g.y;
                gn4.z += v * g.z; gn4.w += v * g.w;
            }
        }
        __syncthreads();
    }

    // stash per-warp partials
    ((float4*)s_agg[w])[lane] = acc;
    if (lane < 16) ((float4*)s_z[w])[lane] = zm4;
    if (lane < 2)  ((float4*)s_gn[w])[lane] = gn4;
    __syncthreads();

    int j = tid;                      // feature index 0..127
    int h = j >> 4;
    int wid = w;

    float aggj = s_agg[0][j] + s_agg[1][j] + s_agg[2][j] + s_agg[3][j];

    // ---- gate[h] = feat.wg[0:128] + zmax.wg[128:192] + nmean-lin ----
    float part[8];
    #pragma unroll
    for (int hh = 0; hh < 8; hh++) part[hh] = 0.f;
    {
        float z = feat[n * DIN + j];
        const float* wr = wg + j * 8;
        #pragma unroll
        for (int hh = 0; hh < 8; hh++) part[hh] += z * wr[hh];
    }
    if (j < DGG) {
        float zmj = fmaxf(fmaxf(s_z[0][j], s_z[1][j]), fmaxf(s_z[2][j], s_z[3][j]));
        float z = (deg > 0) ? zmj : 0.f;
        const float* wr = wg + (128 + j) * 8;
        #pragma unroll
        for (int hh = 0; hh < 8; hh++) part[hh] += z * wr[hh];
    }
    #pragma unroll
    for (int hh = 0; hh < 8; hh++) {
        #pragma unroll
        for (int off = 16; off > 0; off >>= 1)
            part[hh] += __shfl_down_sync(0xffffffffu, part[hh], off);
    }
    if (lane == 0) {
        #pragma unroll
        for (int hh = 0; hh < 8; hh++) wred[wid][hh] = part[hh];
    }
    __syncthreads();
    if (j < 8) {
        float gnm = s_gn[0][j] + s_gn[1][j] + s_gn[2][j] + s_gn[3][j];
        s_gate[j] = wred[0][j] + wred[1][j] + wred[2][j] + wred[3][j] + gnm;
    }
    __syncthreads();

    // ---- norm + output ----
    float h0j = g_f0[n * DOUT + j];
    float h1j = aggj * s_gate[h];

    float s0 = h0j, q0 = h0j * h0j, s1 = h1j, q1 = h1j * h1j;
    #pragma unroll
    for (int off = 16; off > 0; off >>= 1) {
        s0 += __shfl_down_sync(0xffffffffu, s0, off);
        q0 += __shfl_down_sync(0xffffffffu, q0, off);
        s1 += __shfl_down_sync(0xffffffffu, s1, off);
        q1 += __shfl_down_sync(0xffffffffu, q1, off);
    }
    if (lane == 0) {
        red[wid][0] = s0; red[wid][1] = q0; red[wid][2] = s1; red[wid][3] = q1;
    }
    __syncthreads();
    if (j == 0) {
        float S0 = 0, Q0 = 0, S1 = 0, Q1 = 0;
        #pragma unroll
        for (int ww = 0; ww < 4; ww++) {
            S0 += red[ww][0]; Q0 += red[ww][1]; S1 += red[ww][2]; Q1 += red[ww][3];
        }
        float mu0 = S0 * (1.f / DOUT);
        float mu1 = S1 * (1.f / DOUT);
        float v0  = Q0 * (1.f / DOUT) - mu0 * mu0 + 1e-9f;
        float v1  = Q1 * (1.f / DOUT) - mu1 * mu1 + 1e-9f;
        stats[0] = mu0; stats[1] = rsqrtf(v0);
        stats[2] = mu1; stats[3] = rsqrtf(v1);
    }
    __syncthreads();

    float o0 = (h0j - stats[0]) * stats[1] * scale[j]        + offset[j];
    float o1 = (h1j - stats[2]) * stats[3] * scale[DOUT + j] + offset[DOUT + j];
    out[n * DOUT + j] = o0 + o1;
}

// ---------------- launch ----------------
// Launch order rearranged (dependency-safe) so ncu's fixed capture slot lands
// on k_gemm instead of k_scatter: pack, zero, hist, GEMM, scan, scatter, att, main.
extern "C" void kernel_launch(void* const* d_in, const int* in_sizes, int n_in,
                              void* d_out, int out_size) {
    const int*   row    = (const int*)d_in[0];
    const int*   col    = (const int*)d_in[1];
    const float* val    = (const float*)d_in[2];
    const float* feat   = (const float*)d_in[3];
    const float* W      = (const float*)d_in[4];
    const float* b      = (const float*)d_in[5];
    const float* att    = (const float*)d_in[6];
    const float* offset = (const float*)d_in[7];
    const float* scale  = (const float*)d_in[8];
    const float* wg     = (const float*)d_in[9];
    const float* wpg    = (const float*)d_in[10];
    float* out = (float*)d_out;

    k_pack<<<(DIN * BCOLS + 255) / 256, 256>>>(wpg, W, wg);         // 1
    k_zero_cnt<<<(NN + 255) / 256, 256>>>();                        // 2
    k_hist<<<(EE + 255) / 256, 256>>>(row);                         // 3
    k_gemm<<<(NN + RTILE - 1) / RTILE, 256>>>(feat, b);             // 4 <- ncu slot
    k_scan<<<1, 1024>>>();                                          // 5
    k_scatter<<<(EE + 255) / 256, 256>>>(row, col, val);            // 6
    k_att<<<(NN * HH + 255) / 256, 256>>>(att);                     // 7
    k_main<<<NN, 128>>>(feat, wg, scale, offset, out);              // 8
}

// round 11
// speedup vs baseline: 1.6038x; 1.1339x over previous
#include <cuda_runtime.h>
#include <math_constants.h>
#include <cstdint>

// Problem constants (fixed by the reference setup)
#define NN    50000
#define EE    1600000
#define DIN   128
#define DOUT  128
#define HH    8
#define DHH   16
#define DGG   64
#define BCOLS 352   // packed B: 64 zj | 128 f0 | 128 f1 | 8 fz | 24 zero-pad

// ---------------- device scratch (no allocation allowed) ----------------
__device__ float  g_B[DIN * BCOLS];    // prepacked GEMM B (zero-padded)
__device__ float  g_zj[NN * DGG];      // feat @ Wpg              [N,64]
__device__ float  g_f0[NN * DOUT];     // relu(feat@W0 + b0)      [N,128]
__device__ float  g_f1[NN * DOUT];     // relu(feat@W1 + b1)      [N,128]
__device__ float  g_fz[NN * HH];       // feat @ wg[192:320]      [N,8]
__device__ float  g_aself[NN * HH];    // leaky(f0 . att_self)    [N,8]
__device__ float  g_aneigh[NN * HH];   // leaky(f1 . att_neigh)   [N,8]
__device__ int    g_cnt[NN];
__device__ int    g_ptr[NN + 1];
__device__ int    g_pos[NN];
__device__ unsigned long long g_edge[EE];  // packed (val<<32 | col), CSR order

// ---------------- CSR build ----------------
__global__ void k_zero_cnt() {
    int i = blockIdx.x * blockDim.x + threadIdx.x;
    if (i < NN) g_cnt[i] = 0;
}

__global__ void k_hist(const int* __restrict__ row) {
    int i = blockIdx.x * blockDim.x + threadIdx.x;
    if (i < EE) atomicAdd(&g_cnt[row[i]], 1);
}

__global__ void k_scan() {
    __shared__ int wsum[32];
    __shared__ int s_carry;
    int tid  = threadIdx.x;
    int lane = tid & 31;
    int wid  = tid >> 5;
    if (tid == 0) s_carry = 0;
    __syncthreads();
    for (int base = 0; base < NN; base += 1024) {
        int i = base + tid;
        int x = (i < NN) ? g_cnt[i] : 0;
        int v = x;
        #pragma unroll
        for (int off = 1; off < 32; off <<= 1) {
            int t = __shfl_up_sync(0xffffffffu, v, off);
            if (lane >= off) v += t;
        }
        if (lane == 31) wsum[wid] = v;
        __syncthreads();
        if (wid == 0) {
            int s = wsum[lane];
            #pragma unroll
            for (int off = 1; off < 32; off <<= 1) {
                int t = __shfl_up_sync(0xffffffffu, s, off);
                if (lane >= off) s += t;
            }
            wsum[lane] = s;
        }
        __syncthreads();
        int incl  = v + (wid > 0 ? wsum[wid - 1] : 0);
        int carry = s_carry;
        if (i < NN) {
            int e = carry + incl - x;
            g_ptr[i] = e;
            g_pos[i] = e;
        }
        __syncthreads();
        if (tid == 1023) s_carry = carry + incl;
        __syncthreads();
    }
    if (tid == 0) g_ptr[NN] = s_carry;
}

__global__ void k_scatter(const int* __restrict__ row,
                          const int* __restrict__ col,
                          const float* __restrict__ val) {
    int i = blockIdx.x * blockDim.x + threadIdx.x;
    if (i < EE) {
        int p = atomicAdd(&g_pos[row[i]], 1);
        unsigned long long pk =
            ((unsigned long long)__float_as_uint(val[i]) << 32) |
            (unsigned long long)(unsigned)col[i];
        g_edge[p] = pk;
    }
}

// ---------------- pack B once: [128][352] (zeros in pad cols) ----------------
__global__ void k_pack(const float* __restrict__ Wpg,
                       const float* __restrict__ W,
                       const float* __restrict__ wg) {
    int idx = blockIdx.x * blockDim.x + threadIdx.x;
    if (idx >= DIN * BCOLS) return;
    int k = idx / BCOLS, c = idx - k * BCOLS;
    float w = 0.f;
    if (c < DGG) {
        w = Wpg[k * DGG + c];
    } else if (c < 320) {
        int j  = c - DGG;
        int o  = j >> 7;
        int jj = j & 127;
        int h  = jj >> 4, kb = jj & 15;
        w = W[((o * HH + h) * DIN + k) * DHH + kb];
    } else if (c < 328) {
        w = wg[(192 + k) * HH + (c - 320)];
    }
    g_B[idx] = w;
}

// ---------------- tf32 tensor-core GEMM: [N,128] x [128,352] ----------------
__device__ __forceinline__ uint32_t f2tf32(float x) {
    uint32_t t;
    asm("cvt.rna.tf32.f32 %0, %1;" : "=r"(t) : "f"(x));
    return t;
}

__device__ __forceinline__ void mma_tf32(float* d,
                                         uint32_t a0, uint32_t a1, uint32_t a2, uint32_t a3,
                                         uint32_t b0, uint32_t b1) {
    asm volatile(
        "mma.sync.aligned.m16n8k8.row.col.f32.tf32.tf32.f32 "
        "{%0,%1,%2,%3}, {%4,%5,%6,%7}, {%8,%9}, {%0,%1,%2,%3};"
        : "+f"(d[0]), "+f"(d[1]), "+f"(d[2]), "+f"(d[3])
        : "r"(a0), "r"(a1), "r"(a2), "r"(a3), "r"(b0), "r"(b1));
}

__device__ __forceinline__ void gemm_store(int r, int c, float v,
                                           const float* __restrict__ b) {
    if (r >= NN || c >= 328) return;
    if (c < DGG) {
        g_zj[r * DGG + c] = v;
    } else if (c < 320) {
        int jj = c - DGG;                       // 0..255
        float o = fmaxf(v + b[jj], 0.f);
        if (jj < DOUT) g_f0[r * DOUT + jj] = o;
        else           g_f1[r * DOUT + (jj - DOUT)] = o;
    } else {
        g_fz[r * HH + (c - 320)] = v;
    }
}

// Block: 256 threads (8 warps), 32 rows. A tile (32x128 tf32) resident in smem,
// B restaged per 32-col chunk from L2-hot g_B. Warp w: rows (w&1)*16, cols (w>>1)*8
// within each chunk; m16n8k8 per k-step, fp32 accumulate.
__global__ void k_gemm(const float* __restrict__ feat, const float* __restrict__ b) {
    __shared__ uint32_t As[32][132];   // 32 rows x 128 k (+4 pad) tf32
    __shared__ uint32_t Bs[128][40];   // 128 k x 32 cols (+8 pad) tf32

    int tid  = threadIdx.x;
    int w    = tid >> 5;
    int lane = tid & 31;
    int gid  = lane >> 2;              // 0..7
    int tq   = lane & 3;               // 0..3
    int row0 = blockIdx.x * 32;

    // Stage A (convert to tf32): 32 rows x 32 float4
    for (int idx = tid; idx < 32 * 32; idx += 256) {
        int r = idx >> 5, q = idx & 31;
        int gr = row0 + r;
        float4 f = (gr < NN)
            ? *(const float4*)(feat + gr * DIN + q * 4)
            : make_float4(0.f, 0.f, 0.f, 0.f);
        uint4 t;
        t.x = f2tf32(f.x); t.y = f2tf32(f.y);
        t.z = f2tf32(f.z); t.w = f2tf32(f.w);
        *(uint4*)&As[r][q * 4] = t;
    }
    __syncthreads();

    int r_lo = (w & 1) * 16 + gid;     // local row of d0/d1
    int cg   = w >> 1;                 // col group 0..3 (8 cols each)

    for (int nc = 0; nc < 11; nc++) {
        // Stage B chunk (128 k x 32 cols)
        for (int idx = tid; idx < 128 * 8; idx += 256) {
            int k = idx >> 3, q = idx & 7;
            float4 f = *(const float4*)(g_B + k * BCOLS + nc * 32 + q * 4);
            uint4 t;
            t.x = f2tf32(f.x); t.y = f2tf32(f.y);
            t.z = f2tf32(f.z); t.w = f2tf32(f.w);
            *(uint4*)&Bs[k][q * 4] = t;
        }
        __syncthreads();

        float acc[4] = {0.f, 0.f, 0.f, 0.f};
        #pragma unroll
        for (int kk = 0; kk < 128; kk += 8) {
            uint32_t a0 = As[r_lo][kk + tq];
            uint32_t a1 = As[r_lo + 8][kk + tq];
            uint32_t a2 = As[r_lo][kk + tq + 4];
            uint32_t a3 = As[r_lo + 8][kk + tq + 4];
            uint32_t b0 = Bs[kk + tq][cg * 8 + gid];
            uint32_t b1 = Bs[kk + tq + 4][cg * 8 + gid];
            mma_tf32(acc, a0, a1, a2, a3, b0, b1);
        }

        int gr_lo = row0 + r_lo;
        int gr_hi = gr_lo + 8;
        int c0 = nc * 32 + cg * 8 + tq * 2;
        gemm_store(gr_lo, c0,     acc[0], b);
        gemm_store(gr_lo, c0 + 1, acc[1], b);
        gemm_store(gr_hi, c0,     acc[2], b);
        gemm_store(gr_hi, c0 + 1, acc[3], b);
        __syncthreads();   // before Bs overwrite
    }
}

// ---------------- attention scalars ----------------
__device__ __forceinline__ float leaky(float x) {
    return x >= 0.f ? x : 0.2f * x;
}

__global__ void k_att(const float* __restrict__ att) {
    int i = blockIdx.x * blockDim.x + threadIdx.x;
    if (i >= NN * HH) return;
    int n = i >> 3, h = i & 7;
    float s = 0.f, t = 0.f;
    const float* f0p = g_f0 + n * DOUT + h * DHH;
    const float* f1p = g_f1 + n * DOUT + h * DHH;
    const float* ap  = att + h * (2 * DHH);
    #pragma unroll
    for (int k = 0; k < DHH; k++) {
        s += f0p[k] * ap[k];
        t += f1p[k] * ap[DHH + k];
    }
    g_aself[i]  = leaky(s);
    g_aneigh[i] = leaky(t);
}

// ---------------- main per-node kernel (proven block-per-node) ----------------
__global__ void __launch_bounds__(128, 12)
k_main(const float* __restrict__ feat,
       const float* __restrict__ wg,       // [320,8]
       const float* __restrict__ scale,    // [2,128]
       const float* __restrict__ offset,   // [2,128]
       float* __restrict__ out) {
    __shared__ unsigned long long s_e[128];
    __shared__ float s_agg[4][DOUT];
    __shared__ float s_z[4][DGG];
    __shared__ float s_gn[4][HH];
    __shared__ float wred[4][8];
    __shared__ float s_gate[8];
    __shared__ float red[4][4];
    __shared__ float stats[4];

    int n    = blockIdx.x;
    int tid  = threadIdx.x;
    int w    = tid >> 5;
    int lane = tid & 31;

    int e0 = g_ptr[n], e1 = g_ptr[n + 1];
    int deg = e1 - e0;

    int   hlane = lane >> 2;                     // head of this lane's 4 features
    float aself = g_aself[n * HH + hlane];

    float4 acc = make_float4(0.f, 0.f, 0.f, 0.f);
    float4 zm4 = make_float4(-CUDART_INF_F, -CUDART_INF_F, -CUDART_INF_F, -CUDART_INF_F);
    float4 gn4 = make_float4(0.f, 0.f, 0.f, 0.f);

    for (int chunk = e0; chunk < e1; chunk += 128) {
        int m = min(128, e1 - chunk);
        if (tid < m) s_e[tid] = g_edge[chunk + tid];
        __syncthreads();
        #pragma unroll 2
        for (int i = w; i < m; i += 4) {
            unsigned long long pk = s_e[i];
            int   c = (int)(unsigned)(pk & 0xffffffffull);
            float v = __uint_as_float((unsigned)(pk >> 32));
            float a = (aself + g_aneigh[c * HH + hlane]) * v;
            float4 f = *((const float4*)(g_f1 + c * DOUT) + lane);
            acc.x += a * f.x; acc.y += a * f.y;
            acc.z += a * f.z; acc.w += a * f.w;
            if (lane < 16) {
                float4 z = *((const float4*)(g_zj + c * DGG) + lane);
                zm4.x = fmaxf(zm4.x, z.x); zm4.y = fmaxf(zm4.y, z.y);
                zm4.z = fmaxf(zm4.z, z.z); zm4.w = fmaxf(zm4.w, z.w);
            }
            if (lane < 2) {
                float4 g = *((const float4*)(g_fz + c * HH) + lane);
                gn4.x += v * g.x; gn4.y += v * g.y;
                gn4.z += v * g.z; gn4.w += v * g.w;
            }
        }
        __syncthreads();
    }

    // stash per-warp partials
    ((float4*)s_agg[w])[lane] = acc;
    if (lane < 16) ((float4*)s_z[w])[lane] = zm4;
    if (lane < 2)  ((float4*)s_gn[w])[lane] = gn4;
    __syncthreads();

    int j = tid;                      // feature index 0..127
    int h = j >> 4;
    int wid = w;

    float aggj = s_agg[0][j] + s_agg[1][j] + s_agg[2][j] + s_agg[3][j];

    // ---- gate[h] = feat.wg[0:128] + zmax.wg[128:192] + nmean-lin ----
    float part[8];
    #pragma unroll
    for (int hh = 0; hh < 8; hh++) part[hh] = 0.f;
    {
        float z = feat[n * DIN + j];
        const float* wr = wg + j * 8;
        #pragma unroll
        for (int hh = 0; hh < 8; hh++) part[hh] += z * wr[hh];
    }
    if (j < DGG) {
        float zmj = fmaxf(fmaxf(s_z[0][j], s_z[1][j]), fmaxf(s_z[2][j], s_z[3][j]));
        float z = (deg > 0) ? zmj : 0.f;
        const float* wr = wg + (128 + j) * 8;
        #pragma unroll
        for (int hh = 0; hh < 8; hh++) part[hh] += z * wr[hh];
    }
    #pragma unroll
    for (int hh = 0; hh < 8; hh++) {
        #pragma unroll
        for (int off = 16; off > 0; off >>= 1)
            part[hh] += __shfl_down_sync(0xffffffffu, part[hh], off);
    }
    if (lane == 0) {
        #pragma unroll
        for (int hh = 0; hh < 8; hh++) wred[wid][hh] = part[hh];
    }
    __syncthreads();
    if (j < 8) {
        float gnm = s_gn[0][j] + s_gn[1][j] + s_gn[2][j] + s_gn[3][j];
        s_gate[j] = wred[0][j] + wred[1][j] + wred[2][j] + wred[3][j] + gnm;
    }
    __syncthreads();

    // ---- norm + output ----
    float h0j = g_f0[n * DOUT + j];
    float h1j = aggj * s_gate[h];

    float s0 = h0j, q0 = h0j * h0j, s1 = h1j, q1 = h1j * h1j;
    #pragma unroll
    for (int off = 16; off > 0; off >>= 1) {
        s0 += __shfl_down_sync(0xffffffffu, s0, off);
        q0 += __shfl_down_sync(0xffffffffu, q0, off);
        s1 += __shfl_down_sync(0xffffffffu, s1, off);
        q1 += __shfl_down_sync(0xffffffffu, q1, off);
    }
    if (lane == 0) {
        red[wid][0] = s0; red[wid][1] = q0; red[wid][2] = s1; red[wid][3] = q1;
    }
    __syncthreads();
    if (j == 0) {
        float S0 = 0, Q0 = 0, S1 = 0, Q1 = 0;
        #pragma unroll
        for (int ww = 0; ww < 4; ww++) {
            S0 += red[ww][0]; Q0 += red[ww][1]; S1 += red[ww][2]; Q1 += red[ww][3];
        }
        float mu0 = S0 * (1.f / DOUT);
        float mu1 = S1 * (1.f / DOUT);
        float v0  = Q0 * (1.f / DOUT) - mu0 * mu0 + 1e-9f;
        float v1  = Q1 * (1.f / DOUT) - mu1 * mu1 + 1e-9f;
        stats[0] = mu0; stats[1] = rsqrtf(v0);
        stats[2] = mu1; stats[3] = rsqrtf(v1);
    }
    __syncthreads();

    float o0 = (h0j - stats[0]) * stats[1] * scale[j]        + offset[j];
    float o1 = (h1j - stats[2]) * stats[3] * scale[DOUT + j] + offset[DOUT + j];
    out[n * DOUT + j] = o0 + o1;
}

// ---------------- launch ----------------
// Order keeps k_gemm in the ncu capture slot (#4):
// pack, zero, hist, GEMM, scan, scatter, att, main.
extern "C" void kernel_launch(void* const* d_in, const int* in_sizes, int n_in,
                              void* d_out, int out_size) {
    const int*   row    = (const int*)d_in[0];
    const int*   col    = (const int*)d_in[1];
    const float* val    = (const float*)d_in[2];
    const float* feat   = (const float*)d_in[3];
    const float* W      = (const float*)d_in[4];
    const float* b      = (const float*)d_in[5];
    const float* att    = (const float*)d_in[6];
    const float* offset = (const float*)d_in[7];
    const float* scale  = (const float*)d_in[8];
    const float* wg     = (const float*)d_in[9];
    const float* wpg    = (const float*)d_in[10];
    float* out = (float*)d_out;

    k_pack<<<(DIN * BCOLS + 255) / 256, 256>>>(wpg, W, wg);         // 1
    k_zero_cnt<<<(NN + 255) / 256, 256>>>();                        // 2
    k_hist<<<(EE + 255) / 256, 256>>>(row);                         // 3
    k_gemm<<<(NN + 31) / 32, 256>>>(feat, b);                       // 4 <- ncu slot
    k_scan<<<1, 1024>>>();                                          // 5
    k_scatter<<<(EE + 255) / 256, 256>>>(row, col, val);            // 6
    k_att<<<(NN * HH + 255) / 256, 256>>>(att);                     // 7
    k_main<<<NN, 128>>>(feat, wg, scale, offset, out);              // 8
}